// round 4
// baseline (speedup 1.0000x reference)
#include <cuda_runtime.h>
#include <cstdint>

// Problem constants
#define BATCH 4
#define CH    64
#define HH    64
#define WW    64
#define QHH   128
#define QWW   128
#define HID   256
#define OUT3  1728      // C*9*3
#define NK    576       // C*9
#define EPSV  1e-6f

// pw table, transposed: row k (576) x 12 floats [s0o0 s0o1 s0o2 s1o0 ... s3o2]
__device__ float g_pwT[NK * 12];

// ---------------------------------------------------------------------------
// Kernel A: MLP for the 4 parity classes -> g_pwT. Atomic-free, init-free.
// grid = 108 blocks; each block owns 16 OUT3-columns, full j-reduction.
// ---------------------------------------------------------------------------
__global__ void __launch_bounds__(256) mlp_pw_kernel(
    const float* __restrict__ coord, const float* __restrict__ cell,
    const float* __restrict__ w1,    const float* __restrict__ b1,
    const float* __restrict__ w2,    const float* __restrict__ b2)
{
    __shared__ float s_h[4][HID];        // hdd for the 4 parity classes
    __shared__ float s_part[16][16][4];  // [jsub][col][s]

    int tid = threadIdx.x;

    {
        int j = tid;
        #pragma unroll
        for (int s = 0; s < 4; ++s) {
            int py = s >> 1, px = s & 1;
            int qs = py * QWW + px;           // representative query (batch 0)
            float cy = coord[qs * 2 + 0];
            float cx = coord[qs * 2 + 1];
            float ly = cell[qs * 2 + 0];
            float lx = cell[qs * 2 + 1];
            float cy_ = cy - ly * 0.5f;
            float cx_ = cx - lx * 0.5f;
            float cqy = fminf(fmaxf(cy_ + EPSV, -1.0f + EPSV), 1.0f - EPSV);
            float cqx = fminf(fmaxf(cx_ + EPSV, -1.0f + EPSV), 1.0f - EPSV);
            float fy = ((cqy + 1.0f) * 64.0f - 1.0f) * 0.5f;
            float fx = ((cqx + 1.0f) * 64.0f - 1.0f) * 0.5f;
            float iy = fminf(fmaxf(rintf(fy), 0.0f), 63.0f);
            float ix = fminf(fmaxf(rintf(fx), 0.0f), 63.0f);
            float qcy = -1.0f + 2.0f * iy / 64.0f;
            float qcx = -1.0f + 2.0f * ix / 64.0f;
            float ry = (cy_ - qcy) * 32.0f;
            float rx = (cx_ - qcx) * 32.0f;
            float rr = ly * 32.0f;
            float h = ry * w1[j] + rx * w1[HID + j] + rr * w1[2 * HID + j] + b1[j];
            s_h[s][j] = fmaxf(h, 0.0f);
        }
    }
    __syncthreads();

    int col  = tid & 15;                        // 0..15
    int jsub = tid >> 4;                        // 0..15
    int k3   = blockIdx.x * 16 + col;           // 0..1727
    int j0   = jsub * 16;

    float a0 = 0.f, a1 = 0.f, a2 = 0.f, a3 = 0.f;
    const float* wp = w2 + (size_t)j0 * OUT3 + k3;
    #pragma unroll
    for (int j = 0; j < 16; ++j) {
        float w = wp[(size_t)j * OUT3];
        int jj = j0 + j;
        a0 = fmaf(s_h[0][jj], w, a0);
        a1 = fmaf(s_h[1][jj], w, a1);
        a2 = fmaf(s_h[2][jj], w, a2);
        a3 = fmaf(s_h[3][jj], w, a3);
    }
    s_part[jsub][col][0] = a0;
    s_part[jsub][col][1] = a1;
    s_part[jsub][col][2] = a2;
    s_part[jsub][col][3] = a3;
    __syncthreads();

    if (tid < 64) {
        int oc = tid >> 2;          // 0..15
        int os = tid & 3;           // 0..3
        int k3o = blockIdx.x * 16 + oc;
        float v = b2[k3o];
        #pragma unroll
        for (int t = 0; t < 16; ++t) v += s_part[t][oc][os];
        int k = k3o / 3;
        int o = k3o - k * 3;
        g_pwT[k * 12 + os * 3 + o] = v;
    }
}

// ---------------------------------------------------------------------------
// f32x2 packed helpers (FFMA2 — PTX-only on sm_10x)
// ---------------------------------------------------------------------------
__device__ __forceinline__ void ffma2(unsigned long long& d,
                                      unsigned long long a,
                                      unsigned long long b)
{
    asm("fma.rn.f32x2 %0, %1, %2, %0;" : "+l"(d) : "l"(a), "l"(b));
}
__device__ __forceinline__ void addf2(unsigned long long& d, unsigned long long a)
{
    asm("add.rn.f32x2 %0, %0, %1;" : "+l"(d) : "l"(a));
}
__device__ __forceinline__ unsigned long long pack2(float f)
{
    unsigned long long r;
    asm("mov.b64 %0, {%1, %1};" : "=l"(r) : "f"(f));
    return r;
}

// ---------------------------------------------------------------------------
// Kernel B: half-row blocks for occupancy. 512 blocks x 256 threads.
// Block = 32 LR pixels (half a row). k (576 = 64ch x 9taps) split across the
// 8 warps (8 channels each). Lane owns 1 pixel x 12 outputs = 6 f32x2 accs.
// Per tap per lane: 1 LDS.32 + pack + 3 warp-uniform LDS.128 + 6 FFMA2.
// smem = 53.8KB -> 4 blocks/SM -> 32 warps/SM.
// ---------------------------------------------------------------------------
#define TW3  34
#define CHS  (3 * TW3)                  // 102 floats per channel (3 halo rows)
#define TILE_WORDS (CH * CHS)           // 6528
#define PW_WORDS   (NK * 12)            // 6912
#define SMEM_B ((TILE_WORDS + PW_WORDS) * 4)   // 53760 bytes

__global__ void __launch_bounds__(256) metasr_main_kernel(
    const float* __restrict__ feat, float* __restrict__ out)
{
    extern __shared__ float smem[];
    float* s_tile = smem;                  // [64][3][34]
    float* s_pw   = smem + TILE_WORDS;     // [576][12]

    int tid = threadIdx.x;
    int bx  = blockIdx.x;                  // 0..511
    int b   = bx >> 7;
    int rem = bx & 127;
    int y   = rem >> 1;                    // LR row 0..63
    int x0  = (rem & 1) * 32;              // half-row start

    // ---- pw table -> smem (float4) ----
    {
        const float4* src = (const float4*)g_pwT;
        float4* dst = (float4*)s_pw;
        for (int i = tid; i < PW_WORDS / 4; i += 256) dst[i] = src[i];
    }

    const float* fb = feat + (size_t)b * CH * HH * WW;

    // ---- halo columns: tile col 0 (gx = x0-1) and col 33 (gx = x0+32) ----
    for (int i = tid; i < CH * 3 * 2; i += 256) {
        int c    = i / 6;
        int rr   = (i % 6) >> 1;
        int side = i & 1;
        int gy   = y - 1 + rr;
        int gx   = x0 - 1 + side * 33;
        float v = 0.0f;
        if ((unsigned)gy < 64u && (unsigned)gx < 64u)
            v = fb[((c << 6) + gy) * 64 + gx];
        s_tile[c * CHS + rr * TW3 + side * 33] = v;
    }

    // ---- interior: 32 cols per row via float4 loads (scalar STS) ----
    for (int i = tid; i < CH * 3 * 8; i += 256) {     // 1536, 6 iters
        int c   = i / 24;
        int rem2 = i % 24;
        int rr  = rem2 >> 3;
        int q   = rem2 & 7;
        int gy  = y - 1 + rr;
        float4 v = make_float4(0.f, 0.f, 0.f, 0.f);
        if ((unsigned)gy < 64u)
            v = *(const float4*)(fb + ((c << 6) + gy) * 64 + x0 + q * 4);
        float* dst = s_tile + c * CHS + rr * TW3 + 1 + q * 4;
        dst[0] = v.x; dst[1] = v.y; dst[2] = v.z; dst[3] = v.w;
    }
    __syncthreads();

    // ---- main loop ----
    int w    = tid >> 5;
    int lane = tid & 31;

    const float* tc0 = s_tile + (w << 3) * CHS;          // warp's 8 channels
    const ulonglong2* pk0 = (const ulonglong2*)s_pw + (w * 72) * 3;

    unsigned long long acc[6];
    #pragma unroll
    for (int i = 0; i < 6; ++i) acc[i] = 0ull;

    #pragma unroll
    for (int cc = 0; cc < 8; ++cc) {
        const float* tc = tc0 + cc * CHS;
        const ulonglong2* pc = pk0 + cc * 27;   // 9 taps * 3 ull2
        #pragma unroll
        for (int t = 0; t < 9; ++t) {
            const int off = (t / 3) * TW3 + (t % 3);
            unsigned long long F = pack2(tc[off + lane]);
            ulonglong2 p01 = pc[t * 3 + 0];
            ulonglong2 p23 = pc[t * 3 + 1];
            ulonglong2 p45 = pc[t * 3 + 2];
            ffma2(acc[0], F, p01.x); ffma2(acc[1], F, p01.y);
            ffma2(acc[2], F, p23.x); ffma2(acc[3], F, p23.y);
            ffma2(acc[4], F, p45.x); ffma2(acc[5], F, p45.y);
        }
    }

    // ---- cross-warp reduction: s_red[w][a(6)][33] padded, conflict-light ----
    __syncthreads();
    unsigned long long* s_red = (unsigned long long*)smem;
    #pragma unroll
    for (int a = 0; a < 6; ++a)
        s_red[(w * 6 + a) * 33 + lane] = acc[a];
    __syncthreads();

    // pass 2: 192 output ull (32 pixels x 6); thread -> (pixel p, a)
    if (tid < 192) {
        int p  = tid / 6;
        int a  = tid % 6;
        int py = a / 3;              // which HR row of the 2x2
        int jj = a % 3;              // which ull within that row's 6 floats

        unsigned long long v = s_red[a * 33 + p];
        #pragma unroll
        for (int ww = 1; ww < 8; ++ww)
            addf2(v, s_red[(ww * 6 + a) * 33 + p]);

        int yq = 2 * y + py;
        int xq = 2 * (x0 + p);
        size_t base = ((size_t)(b * QHH + yq) * QWW + xq) * 3 + jj * 2;
        *(unsigned long long*)(out + base) = v;
    }
}

// ---------------------------------------------------------------------------
extern "C" void kernel_launch(void* const* d_in, const int* in_sizes, int n_in,
                              void* d_out, int out_size)
{
    const float* feat  = (const float*)d_in[0];
    const float* coord = (const float*)d_in[1];
    const float* cell  = (const float*)d_in[2];
    const float* w1    = (const float*)d_in[3];
    const float* b1    = (const float*)d_in[4];
    const float* w2    = (const float*)d_in[5];
    const float* b2    = (const float*)d_in[6];
    float* out = (float*)d_out;

    cudaFuncSetAttribute(metasr_main_kernel,
                         cudaFuncAttributeMaxDynamicSharedMemorySize, SMEM_B);

    mlp_pw_kernel<<<108, 256>>>(coord, cell, w1, b1, w2, b2);
    metasr_main_kernel<<<512, 256, SMEM_B>>>(feat, out);
}